// round 13
// baseline (speedup 1.0000x reference)
#include <cuda_runtime.h>
#include <cuda_fp16.h>
#include <math.h>

#define N_NODES 50000
#define N_EDGES 800000
#define DIN 128
#define SCAN_BLOCKS 196   // ceil(50000/256)

// ---------------- scratch (no cudaMalloc allowed) ----------------
__device__ __half g_h0[N_NODES * DIN];
__device__ __half g_h1[N_NODES * DIN];
__device__ __half g_xp[N_NODES * DIN];
__device__ __half g_pooled[N_NODES * DIN];
__device__ __half g_hs[N_NODES * DIN];     // h @ Ws (pre-pool partial, fp16)
__device__ __half g_w [131072];            // all 9 weight matrices in fp16
__device__ int    g_rowptr[N_NODES + 1];
__device__ int    g_cursor[N_NODES];
__device__ int    g_bsum[256];
__device__ int    g_csr[N_EDGES];

// fp16 weight offsets inside g_w
#define OFF_WP0 0
#define OFF_WP1 16384
#define OFF_WP2 32768
#define OFF_WS0 49152
#define OFF_WS1 65536
#define OFF_WS2 81920
#define OFF_WN0 90112
#define OFF_WN1 106496
#define OFF_WN2 122880

struct alignas(8) H4 { __half2 a, b; };

struct WConv {
    const float* src[9];
    int off[9];
    int n[9];
};

#define EDGE8_BLOCKS 391   // ceil(100000/256)
#define WCVT_BLOCKS 64

// ---------------- weight convert only (x handled inside fused1 L1) ----------
__global__ void wconv_kernel(WConv wc) {
    int base = blockIdx.x * 256 + threadIdx.x;
    int stride = WCVT_BLOCKS * 256;
    #pragma unroll
    for (int s = 0; s < 9; s++) {
        for (int i = base; i < wc.n[s]; i += stride)
            g_w[wc.off[s] + i] = __float2half(wc.src[s][i]);
    }
}

__global__ void count_deg_kernel(const int4* __restrict__ dst4) {
    int i = blockIdx.x * blockDim.x + threadIdx.x;
    int j = 2 * i;
    if (j < N_EDGES / 4) {
        int4 d0 = dst4[j];
        int4 d1 = dst4[j + 1];
        atomicAdd(&g_cursor[d0.x], 1);
        atomicAdd(&g_cursor[d0.y], 1);
        atomicAdd(&g_cursor[d0.z], 1);
        atomicAdd(&g_cursor[d0.w], 1);
        atomicAdd(&g_cursor[d1.x], 1);
        atomicAdd(&g_cursor[d1.y], 1);
        atomicAdd(&g_cursor[d1.z], 1);
        atomicAdd(&g_cursor[d1.w], 1);
    }
}

// ---- scan: per-block scan -> (add_offsets with inline bsum reduce) ----
__device__ __forceinline__ int block_excl_scan_256(int v, int tid, int* total) {
    int lane = tid & 31, w = tid >> 5;
    int inc = v;
    #pragma unroll
    for (int off = 1; off < 32; off <<= 1) {
        int t = __shfl_up_sync(0xffffffffu, inc, off);
        if (lane >= off) inc += t;
    }
    __shared__ int wsum[8];
    if (lane == 31) wsum[w] = inc;
    __syncthreads();
    if (w == 0 && lane < 8) {
        int x = wsum[lane];
        #pragma unroll
        for (int off = 1; off < 8; off <<= 1) {
            int t = __shfl_up_sync(0x000000ffu, x, off);
            if (lane >= off) x += t;
        }
        wsum[lane] = x;
    }
    __syncthreads();
    int base = (w > 0) ? wsum[w - 1] : 0;
    *total = wsum[7];
    return inc - v + base;
}

__device__ __forceinline__ int block_reduce_sum_256(int v, int tid) {
    int lane = tid & 31, w = tid >> 5;
    #pragma unroll
    for (int off = 16; off > 0; off >>= 1) v += __shfl_xor_sync(0xffffffffu, v, off);
    __shared__ int ws[8];
    if (lane == 0) ws[w] = v;
    __syncthreads();
    if (w == 0) {
        int x = (lane < 8) ? ws[lane] : 0;
        #pragma unroll
        for (int off = 4; off > 0; off >>= 1) x += __shfl_xor_sync(0xffffffffu, x, off);
        if (lane == 0) ws[0] = x;
    }
    __syncthreads();
    return ws[0];
}

__global__ void scan_blocks_kernel() {
    int tid = threadIdx.x;
    int i = blockIdx.x * 256 + tid;
    int v = (i < N_NODES) ? g_cursor[i] : 0;
    int total;
    int excl = block_excl_scan_256(v, tid, &total);
    if (i < N_NODES) g_rowptr[i] = excl;
    if (tid == 0) g_bsum[blockIdx.x] = total;
}

__global__ void add_offsets_kernel() {
    int tid = threadIdx.x;
    int bid = blockIdx.x;
    int vb = (tid < SCAN_BLOCKS && tid < bid) ? g_bsum[tid] : 0;
    int off = block_reduce_sum_256(vb, tid);
    __syncthreads();
    int i = bid * 256 + tid;
    if (i < N_NODES) {
        int r = g_rowptr[i] + off;
        g_rowptr[i] = r;
        g_cursor[i] = r;
    }
    if (bid == SCAN_BLOCKS - 1 && tid == 0) g_rowptr[N_NODES] = N_EDGES;
}

__global__ void scatter_kernel(const int4* __restrict__ src4, const int4* __restrict__ dst4) {
    int i = blockIdx.x * blockDim.x + threadIdx.x;
    int j = 2 * i;
    if (j < N_EDGES / 4) {
        int4 s0 = src4[j];
        int4 d0 = dst4[j];
        int4 s1 = src4[j + 1];
        int4 d1 = dst4[j + 1];
        int p0 = atomicAdd(&g_cursor[d0.x], 1);
        int p1 = atomicAdd(&g_cursor[d0.y], 1);
        int p2 = atomicAdd(&g_cursor[d0.z], 1);
        int p3 = atomicAdd(&g_cursor[d0.w], 1);
        int p4 = atomicAdd(&g_cursor[d1.x], 1);
        int p5 = atomicAdd(&g_cursor[d1.y], 1);
        int p6 = atomicAdd(&g_cursor[d1.z], 1);
        int p7 = atomicAdd(&g_cursor[d1.w], 1);
        g_csr[p0] = s0.x; g_csr[p1] = s0.y; g_csr[p2] = s0.z; g_csr[p3] = s0.w;
        g_csr[p4] = s1.x; g_csr[p5] = s1.y; g_csr[p6] = s1.z; g_csr[p7] = s1.w;
    }
}

// ---------------- pooling: per-node warp max over CSR neighbors (fp16) --------
// relu output >= 0, so 0-init max == segment_max (deg==0 -> 0, matching ref)
__global__ void pool_kernel() {
    int node = (blockIdx.x * blockDim.x + threadIdx.x) >> 5;
    int lane = threadIdx.x & 31;
    if (node >= N_NODES) return;
    int s = g_rowptr[node];
    int e = g_rowptr[node + 1];
    __half2 m0 = __float2half2_rn(0.f), m1 = m0;
    int j = s;
    for (; j + 4 <= e; j += 4) {
        int i0 = g_csr[j], i1 = g_csr[j + 1], i2 = g_csr[j + 2], i3 = g_csr[j + 3];
        H4 v0 = *reinterpret_cast<const H4*>(g_xp + (size_t)i0 * DIN + lane * 4);
        H4 v1 = *reinterpret_cast<const H4*>(g_xp + (size_t)i1 * DIN + lane * 4);
        H4 v2 = *reinterpret_cast<const H4*>(g_xp + (size_t)i2 * DIN + lane * 4);
        H4 v3 = *reinterpret_cast<const H4*>(g_xp + (size_t)i3 * DIN + lane * 4);
        m0 = __hmax2(m0, v0.a); m1 = __hmax2(m1, v0.b);
        m0 = __hmax2(m0, v1.a); m1 = __hmax2(m1, v1.b);
        m0 = __hmax2(m0, v2.a); m1 = __hmax2(m1, v2.b);
        m0 = __hmax2(m0, v3.a); m1 = __hmax2(m1, v3.b);
    }
    for (; j < e; j++) {
        int i0 = g_csr[j];
        H4 v = *reinterpret_cast<const H4*>(g_xp + (size_t)i0 * DIN + lane * 4);
        m0 = __hmax2(m0, v.a); m1 = __hmax2(m1, v.b);
    }
    H4 o; o.a = m0; o.b = m1;
    *reinterpret_cast<H4*>(g_pooled + (size_t)node * DIN + lane * 4) = o;
}

// ---------------- fp16 tensor-core primitives ----------------
__device__ __forceinline__ void ldsm_x4(unsigned& r0, unsigned& r1, unsigned& r2, unsigned& r3,
                                        unsigned addr) {
    asm volatile("ldmatrix.sync.aligned.m8n8.x4.shared.b16 {%0,%1,%2,%3}, [%4];"
                 : "=r"(r0), "=r"(r1), "=r"(r2), "=r"(r3) : "r"(addr));
}
__device__ __forceinline__ void ldsm_x4_t(unsigned& r0, unsigned& r1, unsigned& r2, unsigned& r3,
                                          unsigned addr) {
    asm volatile("ldmatrix.sync.aligned.m8n8.x4.trans.shared.b16 {%0,%1,%2,%3}, [%4];"
                 : "=r"(r0), "=r"(r1), "=r"(r2), "=r"(r3) : "r"(addr));
}
__device__ __forceinline__ void mma_f16(float& d0, float& d1, float& d2, float& d3,
                                        unsigned a0, unsigned a1, unsigned a2, unsigned a3,
                                        unsigned b0, unsigned b1) {
    asm volatile(
        "mma.sync.aligned.m16n8k16.row.col.f32.f16.f16.f32 "
        "{%0,%1,%2,%3}, {%4,%5,%6,%7}, {%8,%9}, {%0,%1,%2,%3};"
        : "+f"(d0), "+f"(d1), "+f"(d2), "+f"(d3)
        : "r"(a0), "r"(a1), "r"(a2), "r"(a3), "r"(b0), "r"(b1));
}

// Smem strides (halves). 272B / 144B rows -> conflict-free LDSM phases.
#define AST1 136
#define BST128 136
#define BST64 72

// ============ kernel1: fused xp/hs GEMM — full-K staging, ONE barrier ============
// chunk id by = blockIdx.y + byoff:
//   by<2  -> xp[:, by*64:+64] = relu(A@Wp + bp)
//   by>=2 -> hs[:, (by-2)*64:+64] = A@Ws (fp16)
// A1FP32: A is fp32 (layer 1); convert to fp16 during staging.
// BM=128, BN=64, K=128, 256 threads, 8 warps (4x2), warp tile 32x32.
template <int DOUTS, bool A1FP32>
__global__ void __launch_bounds__(256)
fused1_kernel(const void* __restrict__ Av,
              const __half* __restrict__ WpH, const float* __restrict__ bp,
              const __half* __restrict__ WsH,
              __half* __restrict__ xp, __half* __restrict__ hs, int byoff)
{
    constexpr int ASZ = 128 * AST1;
    extern __shared__ __half dsm[];
    __half* As = dsm;
    __half* Bs = dsm + ASZ;

    int tid = threadIdx.x;
    int lane = tid & 31, wid = tid >> 5;
    int lr = lane >> 2, lc = lane & 3;
    int l15 = lane & 15, lhi8 = (lane >> 4) << 3;
    int wr = wid >> 1, wc = wid & 1;
    int mbase = wr * 32;
    int nbase = wc * 32;
    int blockRow = blockIdx.x * 128;
    int by = blockIdx.y + byoff;
    bool isWp = by < 2;
    int coff = isWp ? by * 64 : (by - 2) * 64;
    const __half* B = (isWp ? WpH : WsH) + coff;
    int ldB = isWp ? 128 : DOUTS;

    // ---- stage A ----
    if (A1FP32) {
        const float* A = (const float*)Av;
        #pragma unroll
        for (int i = 0; i < 16; i++) {
            int f = tid + i * 256;
            int row = f >> 5, q = f & 31;       // 32 float4 per 128-float row
            int gr = blockRow + row; if (gr >= N_NODES) gr = N_NODES - 1;
            float4 v = *reinterpret_cast<const float4*>(A + (size_t)gr * DIN + q * 4);
            __half2 lo = __floats2half2_rn(v.x, v.y);
            __half2 hi = __floats2half2_rn(v.z, v.w);
            *reinterpret_cast<__half2*>(As + row * AST1 + q * 4)     = lo;
            *reinterpret_cast<__half2*>(As + row * AST1 + q * 4 + 2) = hi;
        }
    } else {
        const __half* A = (const __half*)Av;
        #pragma unroll
        for (int i = 0; i < 8; i++) {
            int f = tid + i * 256;
            int row = f >> 4, q = f & 15;
            int gr = blockRow + row; if (gr >= N_NODES) gr = N_NODES - 1;
            *reinterpret_cast<uint4*>(As + row * AST1 + q * 8) =
                *reinterpret_cast<const uint4*>(A + (size_t)gr * DIN + q * 8);
        }
    }
    // ---- stage B ----
    #pragma unroll
    for (int i = 0; i < 4; i++) {
        int f = tid + i * 256;
        int brow = f >> 3, bq = f & 7;
        *reinterpret_cast<uint4*>(Bs + brow * BST64 + bq * 8) =
            *reinterpret_cast<const uint4*>(B + (size_t)brow * ldB + bq * 8);
    }
    __syncthreads();

    float acc[2][4][4];
    #pragma unroll
    for (int mt = 0; mt < 2; mt++)
        #pragma unroll
        for (int nt = 0; nt < 4; nt++)
            #pragma unroll
            for (int r = 0; r < 4; r++) acc[mt][nt][r] = 0.f;

    unsigned abase = (unsigned)__cvta_generic_to_shared(As);
    unsigned bbase = (unsigned)__cvta_generic_to_shared(Bs);

    #pragma unroll
    for (int ks = 0; ks < 8; ks++) {
        int kk = ks * 16;
        unsigned af[2][4];
        #pragma unroll
        for (int mt = 0; mt < 2; mt++) {
            unsigned addr = abase + 2 * ((mbase + mt * 16 + l15) * AST1 + kk + lhi8);
            ldsm_x4(af[mt][0], af[mt][1], af[mt][2], af[mt][3], addr);
        }
        unsigned bf[4][2];
        #pragma unroll
        for (int np = 0; np < 2; np++) {
            unsigned addr = bbase + 2 * ((kk + l15) * BST64 + nbase + np * 16 + lhi8);
            unsigned r0, r1, r2, r3;
            ldsm_x4_t(r0, r1, r2, r3, addr);
            bf[2 * np][0] = r0; bf[2 * np][1] = r1;
            bf[2 * np + 1][0] = r2; bf[2 * np + 1][1] = r3;
        }
        #pragma unroll
        for (int mt = 0; mt < 2; mt++)
            #pragma unroll
            for (int nt = 0; nt < 4; nt++)
                mma_f16(acc[mt][nt][0], acc[mt][nt][1], acc[mt][nt][2], acc[mt][nt][3],
                        af[mt][0], af[mt][1], af[mt][2], af[mt][3],
                        bf[nt][0], bf[nt][1]);
    }

    // ---- epilogue ----
    #pragma unroll
    for (int mt = 0; mt < 2; mt++) {
        int ra = blockRow + mbase + mt * 16 + lr;
        int rb = ra + 8;
        #pragma unroll
        for (int nt = 0; nt < 4; nt++) {
            int cl = nbase + nt * 8 + 2 * lc;
            int gc = coff + cl;
            float v0 = acc[mt][nt][0], v1 = acc[mt][nt][1];
            float v2 = acc[mt][nt][2], v3 = acc[mt][nt][3];
            if (isWp) {
                float2 bv = *reinterpret_cast<const float2*>(bp + gc);
                v0 = fmaxf(v0 + bv.x, 0.f); v1 = fmaxf(v1 + bv.y, 0.f);
                v2 = fmaxf(v2 + bv.x, 0.f); v3 = fmaxf(v3 + bv.y, 0.f);
                if (ra < N_NODES)
                    *reinterpret_cast<__half2*>(xp + (size_t)ra * DIN + gc) = __floats2half2_rn(v0, v1);
                if (rb < N_NODES)
                    *reinterpret_cast<__half2*>(xp + (size_t)rb * DIN + gc) = __floats2half2_rn(v2, v3);
            } else {
                if (ra < N_NODES)
                    *reinterpret_cast<__half2*>(hs + (size_t)ra * DOUTS + gc) = __floats2half2_rn(v0, v1);
                if (rb < N_NODES)
                    *reinterpret_cast<__half2*>(hs + (size_t)rb * DOUTS + gc) = __floats2half2_rn(v2, v3);
            }
        }
    }
}

// ============ kernel2: out = l2norm_relu(hs + pooled@Wn + b) — full-K staging ====
// BM=64, BN=DOUT, K=128, 256 threads, 8 warps (4x2), warp tile 16x(BN/2).
template <int DOUT, bool OUTHALF>
__global__ void __launch_bounds__(256)
fused2_kernel(const __half* __restrict__ pooled, const __half* __restrict__ WnH,
              const float* __restrict__ bias, const __half* __restrict__ hs,
              void* __restrict__ outv)
{
    constexpr int BM = 64, BN = DOUT;
    constexpr int NT = BN / 16;              // 8 / 4
    constexpr int BST = (BN == 128) ? BST128 : BST64;
    constexpr int ASZ = BM * AST1;
    constexpr int ASEG = 4;
    constexpr int BSEG = (128 * BN / 8) / 256;  // 8 / 4

    extern __shared__ __half dsm[];
    __half* As = dsm;
    __half* Bs = dsm + ASZ;
    __shared__ float ssbuf[2][BM];

    int tid = threadIdx.x;
    int lane = tid & 31, wid = tid >> 5;
    int lr = lane >> 2, lc = lane & 3;
    int l15 = lane & 15, lhi8 = (lane >> 4) << 3;
    int wr = wid >> 1, wc = wid & 1;
    int mbase = wr * 16;
    int nbase = wc * (BN / 2);
    int blockRow = blockIdx.x * BM;

    // ---- stage everything ----
    #pragma unroll
    for (int i = 0; i < ASEG; i++) {
        int f = tid + i * 256;
        int row = f >> 4, q = f & 15;
        int gr = blockRow + row; if (gr >= N_NODES) gr = N_NODES - 1;
        *reinterpret_cast<uint4*>(As + row * AST1 + q * 8) =
            *reinterpret_cast<const uint4*>(pooled + (size_t)gr * DIN + q * 8);
    }
    #pragma unroll
    for (int i = 0; i < BSEG; i++) {
        int f = tid + i * 256;
        int brow = f / (BN / 8), bq = f % (BN / 8);
        *reinterpret_cast<uint4*>(Bs + brow * BST + bq * 8) =
            *reinterpret_cast<const uint4*>(WnH + (size_t)brow * BN + bq * 8);
    }
    __syncthreads();

    float acc[NT][4];
    #pragma unroll
    for (int nt = 0; nt < NT; nt++)
        #pragma unroll
        for (int r = 0; r < 4; r++) acc[nt][r] = 0.f;

    unsigned abase = (unsigned)__cvta_generic_to_shared(As);
    unsigned bbase = (unsigned)__cvta_generic_to_shared(Bs);

    #pragma unroll
    for (int ks = 0; ks < 8; ks++) {
        int kk = ks * 16;
        unsigned af[4];
        {
            unsigned addr = abase + 2 * ((mbase + l15) * AST1 + kk + lhi8);
            ldsm_x4(af[0], af[1], af[2], af[3], addr);
        }
        unsigned bf[NT][2];
        #pragma unroll
        for (int np = 0; np < NT / 2; np++) {
            unsigned addr = bbase + 2 * ((kk + l15) * BST + nbase + np * 16 + lhi8);
            unsigned r0, r1, r2, r3;
            ldsm_x4_t(r0, r1, r2, r3, addr);
            bf[2 * np][0] = r0; bf[2 * np][1] = r1;
            bf[2 * np + 1][0] = r2; bf[2 * np + 1][1] = r3;
        }
        #pragma unroll
        for (int nt = 0; nt < NT; nt++)
            mma_f16(acc[nt][0], acc[nt][1], acc[nt][2], acc[nt][3],
                    af[0], af[1], af[2], af[3], bf[nt][0], bf[nt][1]);
    }

    // ---- epilogue: + hs(fp16) + bias, row L2-norm, relu ----
    int ra = blockRow + mbase + lr;
    int rb = ra + 8;
    #pragma unroll
    for (int nt = 0; nt < NT; nt++) {
        int col = nbase + nt * 8 + 2 * lc;
        float2 bv = *reinterpret_cast<const float2*>(bias + col);
        float2 h0 = (ra < N_NODES)
            ? __half22float2(*reinterpret_cast<const __half2*>(hs + (size_t)ra * DOUT + col))
            : make_float2(0.f, 0.f);
        float2 h1 = (rb < N_NODES)
            ? __half22float2(*reinterpret_cast<const __half2*>(hs + (size_t)rb * DOUT + col))
            : make_float2(0.f, 0.f);
        acc[nt][0] += bv.x + h0.x; acc[nt][1] += bv.y + h0.y;
        acc[nt][2] += bv.x + h1.x; acc[nt][3] += bv.y + h1.y;
    }

    float ssA = 0.f, ssB = 0.f;
    #pragma unroll
    for (int nt = 0; nt < NT; nt++) {
        ssA += acc[nt][0] * acc[nt][0] + acc[nt][1] * acc[nt][1];
        ssB += acc[nt][2] * acc[nt][2] + acc[nt][3] * acc[nt][3];
    }
    ssA += __shfl_xor_sync(0xffffffffu, ssA, 1);
    ssA += __shfl_xor_sync(0xffffffffu, ssA, 2);
    ssB += __shfl_xor_sync(0xffffffffu, ssB, 1);
    ssB += __shfl_xor_sync(0xffffffffu, ssB, 2);
    int rla = mbase + lr;
    if (lc == 0) { ssbuf[wc][rla] = ssA; ssbuf[wc][rla + 8] = ssB; }
    __syncthreads();
    float inv0 = 1.f / fmaxf(sqrtf(ssbuf[0][rla] + ssbuf[1][rla]), 1e-12f);
    float inv1 = 1.f / fmaxf(sqrtf(ssbuf[0][rla + 8] + ssbuf[1][rla + 8]), 1e-12f);

    #pragma unroll
    for (int nt = 0; nt < NT; nt++) {
        int col = nbase + nt * 8 + 2 * lc;
        float v0 = fmaxf(acc[nt][0] * inv0, 0.f);
        float v1 = fmaxf(acc[nt][1] * inv0, 0.f);
        float v2 = fmaxf(acc[nt][2] * inv1, 0.f);
        float v3 = fmaxf(acc[nt][3] * inv1, 0.f);
        if (OUTHALF) {
            __half* out = (__half*)outv;
            if (ra < N_NODES)
                *reinterpret_cast<__half2*>(out + (size_t)ra * DOUT + col) = __floats2half2_rn(v0, v1);
            if (rb < N_NODES)
                *reinterpret_cast<__half2*>(out + (size_t)rb * DOUT + col) = __floats2half2_rn(v2, v3);
        } else {
            float* out = (float*)outv;
            if (ra < N_NODES)
                *reinterpret_cast<float2*>(out + (size_t)ra * DOUT + col) = make_float2(v0, v1);
            if (rb < N_NODES)
                *reinterpret_cast<float2*>(out + (size_t)rb * DOUT + col) = make_float2(v2, v3);
        }
    }
}

// ---------------- launch ----------------
extern "C" void kernel_launch(void* const* d_in, const int* in_sizes, int n_in,
                              void* d_out, int out_size)
{
    const float* x        = (const float*)d_in[0];
    const int*   edge_src = (const int*)d_in[1];
    const int*   edge_dst = (const int*)d_in[2];

    const float* Wp[3]; const float* bp[3];
    const float* Ws[3]; const float* Wn[3]; const float* bb[3];
    for (int l = 0; l < 3; l++) {
        Wp[l] = (const float*)d_in[3 + 5 * l + 0];
        bp[l] = (const float*)d_in[3 + 5 * l + 1];
        Ws[l] = (const float*)d_in[3 + 5 * l + 2];
        Wn[l] = (const float*)d_in[3 + 5 * l + 3];
        bb[l] = (const float*)d_in[3 + 5 * l + 4];
    }

    float* out = (float*)d_out;

    __half* h0d; cudaGetSymbolAddress((void**)&h0d, g_h0);
    __half* h1d; cudaGetSymbolAddress((void**)&h1d, g_h1);
    __half* xpd; cudaGetSymbolAddress((void**)&xpd, g_xp);
    __half* pld; cudaGetSymbolAddress((void**)&pld, g_pooled);
    __half* hsd; cudaGetSymbolAddress((void**)&hsd, g_hs);
    __half* wd;  cudaGetSymbolAddress((void**)&wd, g_w);
    int* curd;   cudaGetSymbolAddress((void**)&curd, g_cursor);

    const int TPB = 256;
    const int G1_X = (N_NODES + 127) / 128;   // 391
    const int G2_X = (N_NODES + 63) / 64;     // 782
    const int POOL_BLOCKS = (N_NODES * 32 + TPB - 1) / TPB;

    // dynamic smem sizes (bytes)
    const int SMEM1      = (128 * AST1 + 128 * BST64) * 2;           // 53248
    const int SMEM2_128  = (64 * AST1 + 128 * BST128) * 2;           // 52224
    const int SMEM2_64   = (64 * AST1 + 128 * BST64) * 2;            // 35840

    // one-time infra (stream/events are not device memory; results unaffected)
    static cudaStream_t s2 = nullptr;
    static cudaEvent_t eRoot, eCSR, eJ1, eH2, eJ2, eH3;
    if (!s2) {
        cudaStreamCreateWithFlags(&s2, cudaStreamNonBlocking);
        cudaEventCreateWithFlags(&eRoot, cudaEventDisableTiming);
        cudaEventCreateWithFlags(&eCSR,  cudaEventDisableTiming);
        cudaEventCreateWithFlags(&eJ1,   cudaEventDisableTiming);
        cudaEventCreateWithFlags(&eH2,   cudaEventDisableTiming);
        cudaEventCreateWithFlags(&eJ2,   cudaEventDisableTiming);
        cudaEventCreateWithFlags(&eH3,   cudaEventDisableTiming);
        cudaFuncSetAttribute((const void*)fused1_kernel<128, true>,
                             cudaFuncAttributeMaxDynamicSharedMemorySize, SMEM1);
        cudaFuncSetAttribute((const void*)fused1_kernel<128, false>,
                             cudaFuncAttributeMaxDynamicSharedMemorySize, SMEM1);
        cudaFuncSetAttribute((const void*)fused1_kernel<64, false>,
                             cudaFuncAttributeMaxDynamicSharedMemorySize, SMEM1);
        cudaFuncSetAttribute((const void*)fused2_kernel<128, true>,
                             cudaFuncAttributeMaxDynamicSharedMemorySize, SMEM2_128);
        cudaFuncSetAttribute((const void*)fused2_kernel<64, false>,
                             cudaFuncAttributeMaxDynamicSharedMemorySize, SMEM2_64);
    }

    WConv wc;
    wc.src[0] = Wp[0]; wc.off[0] = OFF_WP0; wc.n[0] = 16384;
    wc.src[1] = Wp[1]; wc.off[1] = OFF_WP1; wc.n[1] = 16384;
    wc.src[2] = Wp[2]; wc.off[2] = OFF_WP2; wc.n[2] = 16384;
    wc.src[3] = Ws[0]; wc.off[3] = OFF_WS0; wc.n[3] = 16384;
    wc.src[4] = Ws[1]; wc.off[4] = OFF_WS1; wc.n[4] = 16384;
    wc.src[5] = Ws[2]; wc.off[5] = OFF_WS2; wc.n[5] = 8192;
    wc.src[6] = Wn[0]; wc.off[6] = OFF_WN0; wc.n[6] = 16384;
    wc.src[7] = Wn[1]; wc.off[7] = OFF_WN1; wc.n[7] = 16384;
    wc.src[8] = Wn[2]; wc.off[8] = OFF_WN2; wc.n[8] = 8192;

    // ---- fork: CSR chain on s2, weight convert + layer-1 GEMM on legacy ----
    cudaMemsetAsync(curd, 0, N_NODES * sizeof(int));
    cudaEventRecord(eRoot, 0);
    cudaStreamWaitEvent(s2, eRoot, 0);
    count_deg_kernel<<<EDGE8_BLOCKS, TPB, 0, s2>>>((const int4*)edge_dst);
    scan_blocks_kernel<<<SCAN_BLOCKS, 256, 0, s2>>>();
    add_offsets_kernel<<<SCAN_BLOCKS, 256, 0, s2>>>();
    scatter_kernel<<<EDGE8_BLOCKS, TPB, 0, s2>>>((const int4*)edge_src, (const int4*)edge_dst);
    cudaEventRecord(eCSR, s2);

    wconv_kernel<<<WCVT_BLOCKS, TPB>>>(wc);

    // ---- layer 1 (A = x fp32 directly; pool waits for CSR) ----
    fused1_kernel<128, true><<<dim3(G1_X, 4), TPB, SMEM1>>>(x, wd + OFF_WP0, bp[0], wd + OFF_WS0, xpd, hsd, 0);
    cudaStreamWaitEvent(0, eCSR, 0);
    pool_kernel<<<POOL_BLOCKS, TPB>>>();
    fused2_kernel<128, true><<<G2_X, TPB, SMEM2_128>>>(pld, wd + OFF_WN0, bb[0], hsd, h0d);
    cudaEventRecord(eJ1, 0);

    // ---- layer 2: hs GEMM on s2 overlaps (xp GEMM -> pool) on legacy ----
    cudaStreamWaitEvent(s2, eJ1, 0);
    fused1_kernel<128, false><<<dim3(G1_X, 2), TPB, SMEM1, s2>>>(h0d, wd + OFF_WP1, bp[1], wd + OFF_WS1, xpd, hsd, 2);
    cudaEventRecord(eH2, s2);
    fused1_kernel<128, false><<<dim3(G1_X, 2), TPB, SMEM1>>>(h0d, wd + OFF_WP1, bp[1], wd + OFF_WS1, xpd, hsd, 0);
    pool_kernel<<<POOL_BLOCKS, TPB>>>();
    cudaStreamWaitEvent(0, eH2, 0);
    fused2_kernel<128, true><<<G2_X, TPB, SMEM2_128>>>(pld, wd + OFF_WN1, bb[1], hsd, h1d);
    cudaEventRecord(eJ2, 0);

    // ---- layer 3: same overlap; out fp32 ----
    cudaStreamWaitEvent(s2, eJ2, 0);
    fused1_kernel<64, false><<<dim3(G1_X, 1), TPB, SMEM1, s2>>>(h1d, wd + OFF_WP2, bp[2], wd + OFF_WS2, xpd, hsd, 2);
    cudaEventRecord(eH3, s2);
    fused1_kernel<64, false><<<dim3(G1_X, 2), TPB, SMEM1>>>(h1d, wd + OFF_WP2, bp[2], wd + OFF_WS2, xpd, hsd, 0);
    pool_kernel<<<POOL_BLOCKS, TPB>>>();
    cudaStreamWaitEvent(0, eH3, 0);
    fused2_kernel<64, false><<<G2_X, TPB, SMEM2_64>>>(pld, wd + OFF_WN2, bb[2], hsd, out);
}

// round 14
// speedup vs baseline: 1.0735x; 1.0735x over previous
#include <cuda_runtime.h>
#include <cuda_fp16.h>
#include <math.h>

#define N_NODES 50000
#define N_EDGES 800000
#define DIN 128
#define SCAN_BLOCKS 196   // ceil(50000/256)

// ---------------- scratch (no cudaMalloc allowed) ----------------
__device__ __half g_x [N_NODES * DIN];     // x converted to fp16
__device__ __half g_h0[N_NODES * DIN];
__device__ __half g_h1[N_NODES * DIN];
__device__ __half g_xp[N_NODES * DIN];
__device__ __half g_pooled[N_NODES * DIN];
__device__ __half g_hs[N_NODES * DIN];     // h @ Ws (pre-pool partial, fp16)
__device__ __half g_w [131072];            // all 9 weight matrices in fp16
__device__ int    g_rowptr[N_NODES + 1];
__device__ int    g_cursor[N_NODES];
__device__ int    g_bsum[256];
__device__ int    g_csr[N_EDGES];

// fp16 weight offsets inside g_w
#define OFF_WP0 0
#define OFF_WP1 16384
#define OFF_WP2 32768
#define OFF_WS0 49152
#define OFF_WS1 65536
#define OFF_WS2 81920
#define OFF_WN0 90112
#define OFF_WN1 106496
#define OFF_WN2 122880

struct alignas(8) H4 { __half2 a, b; };

struct WConv {
    const float* src[9];
    int off[9];
    int n[9];
};

#define CVT_BLOCKS 6250    // 50000*128/4/256
#define EDGE4_BLOCKS 782   // ceil(200000/256)
#define WCVT_BLOCKS 64

// ---------------- prep: convert x + convert weights ----------
__global__ void prep_kernel(const float4* __restrict__ x4, WConv wc) {
    int b = blockIdx.x;
    if (b < CVT_BLOCKS) {
        int i = b * 256 + threadIdx.x;
        if (i < N_NODES * DIN / 4) {
            float4 v = x4[i];
            __half2* out2 = reinterpret_cast<__half2*>(g_x);
            out2[2 * i]     = __floats2half2_rn(v.x, v.y);
            out2[2 * i + 1] = __floats2half2_rn(v.z, v.w);
        }
    } else {
        int base = (b - CVT_BLOCKS) * 256 + threadIdx.x;
        int stride = WCVT_BLOCKS * 256;
        #pragma unroll
        for (int s = 0; s < 9; s++) {
            for (int i = base; i < wc.n[s]; i += stride)
                g_w[wc.off[s] + i] = __float2half(wc.src[s][i]);
        }
    }
}

__global__ void count_deg_kernel(const int4* __restrict__ dst4) {
    int i = blockIdx.x * blockDim.x + threadIdx.x;
    if (i < N_EDGES / 4) {
        int4 d = dst4[i];
        atomicAdd(&g_cursor[d.x], 1);
        atomicAdd(&g_cursor[d.y], 1);
        atomicAdd(&g_cursor[d.z], 1);
        atomicAdd(&g_cursor[d.w], 1);
    }
}

// ---- scan: per-block scan -> (add_offsets with inline bsum reduce) ----
__device__ __forceinline__ int block_excl_scan_256(int v, int tid, int* total) {
    int lane = tid & 31, w = tid >> 5;
    int inc = v;
    #pragma unroll
    for (int off = 1; off < 32; off <<= 1) {
        int t = __shfl_up_sync(0xffffffffu, inc, off);
        if (lane >= off) inc += t;
    }
    __shared__ int wsum[8];
    if (lane == 31) wsum[w] = inc;
    __syncthreads();
    if (w == 0 && lane < 8) {
        int x = wsum[lane];
        #pragma unroll
        for (int off = 1; off < 8; off <<= 1) {
            int t = __shfl_up_sync(0x000000ffu, x, off);
            if (lane >= off) x += t;
        }
        wsum[lane] = x;
    }
    __syncthreads();
    int base = (w > 0) ? wsum[w - 1] : 0;
    *total = wsum[7];
    return inc - v + base;
}

__device__ __forceinline__ int block_reduce_sum_256(int v, int tid) {
    int lane = tid & 31, w = tid >> 5;
    #pragma unroll
    for (int off = 16; off > 0; off >>= 1) v += __shfl_xor_sync(0xffffffffu, v, off);
    __shared__ int ws[8];
    if (lane == 0) ws[w] = v;
    __syncthreads();
    if (w == 0) {
        int x = (lane < 8) ? ws[lane] : 0;
        #pragma unroll
        for (int off = 4; off > 0; off >>= 1) x += __shfl_xor_sync(0xffffffffu, x, off);
        if (lane == 0) ws[0] = x;
    }
    __syncthreads();
    return ws[0];
}

__global__ void scan_blocks_kernel() {
    int tid = threadIdx.x;
    int i = blockIdx.x * 256 + tid;
    int v = (i < N_NODES) ? g_cursor[i] : 0;
    int total;
    int excl = block_excl_scan_256(v, tid, &total);
    if (i < N_NODES) g_rowptr[i] = excl;
    if (tid == 0) g_bsum[blockIdx.x] = total;
}

__global__ void add_offsets_kernel() {
    int tid = threadIdx.x;
    int bid = blockIdx.x;
    int vb = (tid < SCAN_BLOCKS && tid < bid) ? g_bsum[tid] : 0;
    int off = block_reduce_sum_256(vb, tid);
    __syncthreads();
    int i = bid * 256 + tid;
    if (i < N_NODES) {
        int r = g_rowptr[i] + off;
        g_rowptr[i] = r;
        g_cursor[i] = r;
    }
    if (bid == SCAN_BLOCKS - 1 && tid == 0) g_rowptr[N_NODES] = N_EDGES;
}

__global__ void scatter_kernel(const int4* __restrict__ src4, const int4* __restrict__ dst4) {
    int i = blockIdx.x * blockDim.x + threadIdx.x;
    if (i < N_EDGES / 4) {
        int4 s = src4[i];
        int4 d = dst4[i];
        int p0 = atomicAdd(&g_cursor[d.x], 1);
        int p1 = atomicAdd(&g_cursor[d.y], 1);
        int p2 = atomicAdd(&g_cursor[d.z], 1);
        int p3 = atomicAdd(&g_cursor[d.w], 1);
        g_csr[p0] = s.x; g_csr[p1] = s.y; g_csr[p2] = s.z; g_csr[p3] = s.w;
    }
}

// ---------------- pooling: per-node warp max over CSR neighbors (fp16) --------
// relu output >= 0, so 0-init max == segment_max (deg==0 -> 0, matching ref)
__global__ void pool_kernel() {
    int node = (blockIdx.x * blockDim.x + threadIdx.x) >> 5;
    int lane = threadIdx.x & 31;
    if (node >= N_NODES) return;
    int s = g_rowptr[node];
    int e = g_rowptr[node + 1];
    __half2 m0 = __float2half2_rn(0.f), m1 = m0;
    int j = s;
    for (; j + 4 <= e; j += 4) {
        int i0 = g_csr[j], i1 = g_csr[j + 1], i2 = g_csr[j + 2], i3 = g_csr[j + 3];
        H4 v0 = *reinterpret_cast<const H4*>(g_xp + (size_t)i0 * DIN + lane * 4);
        H4 v1 = *reinterpret_cast<const H4*>(g_xp + (size_t)i1 * DIN + lane * 4);
        H4 v2 = *reinterpret_cast<const H4*>(g_xp + (size_t)i2 * DIN + lane * 4);
        H4 v3 = *reinterpret_cast<const H4*>(g_xp + (size_t)i3 * DIN + lane * 4);
        m0 = __hmax2(m0, v0.a); m1 = __hmax2(m1, v0.b);
        m0 = __hmax2(m0, v1.a); m1 = __hmax2(m1, v1.b);
        m0 = __hmax2(m0, v2.a); m1 = __hmax2(m1, v2.b);
        m0 = __hmax2(m0, v3.a); m1 = __hmax2(m1, v3.b);
    }
    for (; j < e; j++) {
        int i0 = g_csr[j];
        H4 v = *reinterpret_cast<const H4*>(g_xp + (size_t)i0 * DIN + lane * 4);
        m0 = __hmax2(m0, v.a); m1 = __hmax2(m1, v.b);
    }
    H4 o; o.a = m0; o.b = m1;
    *reinterpret_cast<H4*>(g_pooled + (size_t)node * DIN + lane * 4) = o;
}

// ---------------- fp16 tensor-core primitives ----------------
__device__ __forceinline__ void ldsm_x4(unsigned& r0, unsigned& r1, unsigned& r2, unsigned& r3,
                                        unsigned addr) {
    asm volatile("ldmatrix.sync.aligned.m8n8.x4.shared.b16 {%0,%1,%2,%3}, [%4];"
                 : "=r"(r0), "=r"(r1), "=r"(r2), "=r"(r3) : "r"(addr));
}
__device__ __forceinline__ void ldsm_x4_t(unsigned& r0, unsigned& r1, unsigned& r2, unsigned& r3,
                                          unsigned addr) {
    asm volatile("ldmatrix.sync.aligned.m8n8.x4.trans.shared.b16 {%0,%1,%2,%3}, [%4];"
                 : "=r"(r0), "=r"(r1), "=r"(r2), "=r"(r3) : "r"(addr));
}
__device__ __forceinline__ void mma_f16(float& d0, float& d1, float& d2, float& d3,
                                        unsigned a0, unsigned a1, unsigned a2, unsigned a3,
                                        unsigned b0, unsigned b1) {
    asm volatile(
        "mma.sync.aligned.m16n8k16.row.col.f32.f16.f16.f32 "
        "{%0,%1,%2,%3}, {%4,%5,%6,%7}, {%8,%9}, {%0,%1,%2,%3};"
        : "+f"(d0), "+f"(d1), "+f"(d2), "+f"(d3)
        : "r"(a0), "r"(a1), "r"(a2), "r"(a3), "r"(b0), "r"(b1));
}

// Smem strides (halves). 272B / 144B rows -> conflict-free LDSM phases.
#define AST1 136
#define BST128 136
#define BST64 72

// ============ kernel1: fused xp/hs GEMM — full-K staging, ONE barrier ============
// chunk id by = blockIdx.y + byoff:
//   by<2  -> xp[:, by*64:+64] = relu(A@Wp + bp)
//   by>=2 -> hs[:, (by-2)*64:+64] = A@Ws (fp16)
// BM=128, BN=64, K=128, 256 threads, 8 warps (4x2), warp tile 32x32.
template <int DOUTS>
__global__ void __launch_bounds__(256)
fused1_kernel(const __half* __restrict__ A,
              const __half* __restrict__ WpH, const float* __restrict__ bp,
              const __half* __restrict__ WsH,
              __half* __restrict__ xp, __half* __restrict__ hs, int byoff)
{
    constexpr int ASZ = 128 * AST1;
    extern __shared__ __half dsm[];
    __half* As = dsm;
    __half* Bs = dsm + ASZ;

    int tid = threadIdx.x;
    int lane = tid & 31, wid = tid >> 5;
    int lr = lane >> 2, lc = lane & 3;
    int l15 = lane & 15, lhi8 = (lane >> 4) << 3;
    int wr = wid >> 1, wc = wid & 1;
    int mbase = wr * 32;
    int nbase = wc * 32;
    int blockRow = blockIdx.x * 128;
    int by = blockIdx.y + byoff;
    bool isWp = by < 2;
    int coff = isWp ? by * 64 : (by - 2) * 64;
    const __half* B = (isWp ? WpH : WsH) + coff;
    int ldB = isWp ? 128 : DOUTS;

    // ---- stage everything ----
    #pragma unroll
    for (int i = 0; i < 8; i++) {
        int f = tid + i * 256;
        int row = f >> 4, q = f & 15;
        int gr = blockRow + row; if (gr >= N_NODES) gr = N_NODES - 1;
        *reinterpret_cast<uint4*>(As + row * AST1 + q * 8) =
            *reinterpret_cast<const uint4*>(A + (size_t)gr * DIN + q * 8);
    }
    #pragma unroll
    for (int i = 0; i < 4; i++) {
        int f = tid + i * 256;
        int brow = f >> 3, bq = f & 7;
        *reinterpret_cast<uint4*>(Bs + brow * BST64 + bq * 8) =
            *reinterpret_cast<const uint4*>(B + (size_t)brow * ldB + bq * 8);
    }
    __syncthreads();

    float acc[2][4][4];
    #pragma unroll
    for (int mt = 0; mt < 2; mt++)
        #pragma unroll
        for (int nt = 0; nt < 4; nt++)
            #pragma unroll
            for (int r = 0; r < 4; r++) acc[mt][nt][r] = 0.f;

    unsigned abase = (unsigned)__cvta_generic_to_shared(As);
    unsigned bbase = (unsigned)__cvta_generic_to_shared(Bs);

    #pragma unroll
    for (int ks = 0; ks < 8; ks++) {
        int kk = ks * 16;
        unsigned af[2][4];
        #pragma unroll
        for (int mt = 0; mt < 2; mt++) {
            unsigned addr = abase + 2 * ((mbase + mt * 16 + l15) * AST1 + kk + lhi8);
            ldsm_x4(af[mt][0], af[mt][1], af[mt][2], af[mt][3], addr);
        }
        unsigned bf[4][2];
        #pragma unroll
        for (int np = 0; np < 2; np++) {
            unsigned addr = bbase + 2 * ((kk + l15) * BST64 + nbase + np * 16 + lhi8);
            unsigned r0, r1, r2, r3;
            ldsm_x4_t(r0, r1, r2, r3, addr);
            bf[2 * np][0] = r0; bf[2 * np][1] = r1;
            bf[2 * np + 1][0] = r2; bf[2 * np + 1][1] = r3;
        }
        #pragma unroll
        for (int mt = 0; mt < 2; mt++)
            #pragma unroll
            for (int nt = 0; nt < 4; nt++)
                mma_f16(acc[mt][nt][0], acc[mt][nt][1], acc[mt][nt][2], acc[mt][nt][3],
                        af[mt][0], af[mt][1], af[mt][2], af[mt][3],
                        bf[nt][0], bf[nt][1]);
    }

    // ---- epilogue ----
    #pragma unroll
    for (int mt = 0; mt < 2; mt++) {
        int ra = blockRow + mbase + mt * 16 + lr;
        int rb = ra + 8;
        #pragma unroll
        for (int nt = 0; nt < 4; nt++) {
            int cl = nbase + nt * 8 + 2 * lc;
            int gc = coff + cl;
            float v0 = acc[mt][nt][0], v1 = acc[mt][nt][1];
            float v2 = acc[mt][nt][2], v3 = acc[mt][nt][3];
            if (isWp) {
                float2 bv = *reinterpret_cast<const float2*>(bp + gc);
                v0 = fmaxf(v0 + bv.x, 0.f); v1 = fmaxf(v1 + bv.y, 0.f);
                v2 = fmaxf(v2 + bv.x, 0.f); v3 = fmaxf(v3 + bv.y, 0.f);
                if (ra < N_NODES)
                    *reinterpret_cast<__half2*>(xp + (size_t)ra * DIN + gc) = __floats2half2_rn(v0, v1);
                if (rb < N_NODES)
                    *reinterpret_cast<__half2*>(xp + (size_t)rb * DIN + gc) = __floats2half2_rn(v2, v3);
            } else {
                if (ra < N_NODES)
                    *reinterpret_cast<__half2*>(hs + (size_t)ra * DOUTS + gc) = __floats2half2_rn(v0, v1);
                if (rb < N_NODES)
                    *reinterpret_cast<__half2*>(hs + (size_t)rb * DOUTS + gc) = __floats2half2_rn(v2, v3);
            }
        }
    }
}

// ============ kernel2: out = l2norm_relu(hs + pooled@Wn + b) — full-K staging ====
// BM=64, BN=DOUT, K=128, 256 threads, 8 warps (4x2), warp tile 16x(BN/2).
template <int DOUT, bool OUTHALF>
__global__ void __launch_bounds__(256)
fused2_kernel(const __half* __restrict__ pooled, const __half* __restrict__ WnH,
              const float* __restrict__ bias, const __half* __restrict__ hs,
              void* __restrict__ outv)
{
    constexpr int BM = 64, BN = DOUT;
    constexpr int NT = BN / 16;              // 8 / 4
    constexpr int BST = (BN == 128) ? BST128 : BST64;
    constexpr int ASZ = BM * AST1;
    constexpr int ASEG = 4;
    constexpr int BSEG = (128 * BN / 8) / 256;  // 8 / 4

    extern __shared__ __half dsm[];
    __half* As = dsm;
    __half* Bs = dsm + ASZ;
    __shared__ float ssbuf[2][BM];

    int tid = threadIdx.x;
    int lane = tid & 31, wid = tid >> 5;
    int lr = lane >> 2, lc = lane & 3;
    int l15 = lane & 15, lhi8 = (lane >> 4) << 3;
    int wr = wid >> 1, wc = wid & 1;
    int mbase = wr * 16;
    int nbase = wc * (BN / 2);
    int blockRow = blockIdx.x * BM;

    // ---- stage everything ----
    #pragma unroll
    for (int i = 0; i < ASEG; i++) {
        int f = tid + i * 256;
        int row = f >> 4, q = f & 15;
        int gr = blockRow + row; if (gr >= N_NODES) gr = N_NODES - 1;
        *reinterpret_cast<uint4*>(As + row * AST1 + q * 8) =
            *reinterpret_cast<const uint4*>(pooled + (size_t)gr * DIN + q * 8);
    }
    #pragma unroll
    for (int i = 0; i < BSEG; i++) {
        int f = tid + i * 256;
        int brow = f / (BN / 8), bq = f % (BN / 8);
        *reinterpret_cast<uint4*>(Bs + brow * BST + bq * 8) =
            *reinterpret_cast<const uint4*>(WnH + (size_t)brow * BN + bq * 8);
    }
    __syncthreads();

    float acc[NT][4];
    #pragma unroll
    for (int nt = 0; nt < NT; nt++)
        #pragma unroll
        for (int r = 0; r < 4; r++) acc[nt][r] = 0.f;

    unsigned abase = (unsigned)__cvta_generic_to_shared(As);
    unsigned bbase = (unsigned)__cvta_generic_to_shared(Bs);

    #pragma unroll
    for (int ks = 0; ks < 8; ks++) {
        int kk = ks * 16;
        unsigned af[4];
        {
            unsigned addr = abase + 2 * ((mbase + l15) * AST1 + kk + lhi8);
            ldsm_x4(af[0], af[1], af[2], af[3], addr);
        }
        unsigned bf[NT][2];
        #pragma unroll
        for (int np = 0; np < NT / 2; np++) {
            unsigned addr = bbase + 2 * ((kk + l15) * BST + nbase + np * 16 + lhi8);
            unsigned r0, r1, r2, r3;
            ldsm_x4_t(r0, r1, r2, r3, addr);
            bf[2 * np][0] = r0; bf[2 * np][1] = r1;
            bf[2 * np + 1][0] = r2; bf[2 * np + 1][1] = r3;
        }
        #pragma unroll
        for (int nt = 0; nt < NT; nt++)
            mma_f16(acc[nt][0], acc[nt][1], acc[nt][2], acc[nt][3],
                    af[0], af[1], af[2], af[3], bf[nt][0], bf[nt][1]);
    }

    // ---- epilogue: + hs(fp16) + bias, row L2-norm, relu ----
    int ra = blockRow + mbase + lr;
    int rb = ra + 8;
    #pragma unroll
    for (int nt = 0; nt < NT; nt++) {
        int col = nbase + nt * 8 + 2 * lc;
        float2 bv = *reinterpret_cast<const float2*>(bias + col);
        float2 h0 = (ra < N_NODES)
            ? __half22float2(*reinterpret_cast<const __half2*>(hs + (size_t)ra * DOUT + col))
            : make_float2(0.f, 0.f);
        float2 h1 = (rb < N_NODES)
            ? __half22float2(*reinterpret_cast<const __half2*>(hs + (size_t)rb * DOUT + col))
            : make_float2(0.f, 0.f);
        acc[nt][0] += bv.x + h0.x; acc[nt][1] += bv.y + h0.y;
        acc[nt][2] += bv.x + h1.x; acc[nt][3] += bv.y + h1.y;
    }

    float ssA = 0.f, ssB = 0.f;
    #pragma unroll
    for (int nt = 0; nt < NT; nt++) {
        ssA += acc[nt][0] * acc[nt][0] + acc[nt][1] * acc[nt][1];
        ssB += acc[nt][2] * acc[nt][2] + acc[nt][3] * acc[nt][3];
    }
    ssA += __shfl_xor_sync(0xffffffffu, ssA, 1);
    ssA += __shfl_xor_sync(0xffffffffu, ssA, 2);
    ssB += __shfl_xor_sync(0xffffffffu, ssB, 1);
    ssB += __shfl_xor_sync(0xffffffffu, ssB, 2);
    int rla = mbase + lr;
    if (lc == 0) { ssbuf[wc][rla] = ssA; ssbuf[wc][rla + 8] = ssB; }
    __syncthreads();
    float inv0 = 1.f / fmaxf(sqrtf(ssbuf[0][rla] + ssbuf[1][rla]), 1e-12f);
    float inv1 = 1.f / fmaxf(sqrtf(ssbuf[0][rla + 8] + ssbuf[1][rla + 8]), 1e-12f);

    #pragma unroll
    for (int nt = 0; nt < NT; nt++) {
        int col = nbase + nt * 8 + 2 * lc;
        float v0 = fmaxf(acc[nt][0] * inv0, 0.f);
        float v1 = fmaxf(acc[nt][1] * inv0, 0.f);
        float v2 = fmaxf(acc[nt][2] * inv1, 0.f);
        float v3 = fmaxf(acc[nt][3] * inv1, 0.f);
        if (OUTHALF) {
            __half* out = (__half*)outv;
            if (ra < N_NODES)
                *reinterpret_cast<__half2*>(out + (size_t)ra * DOUT + col) = __floats2half2_rn(v0, v1);
            if (rb < N_NODES)
                *reinterpret_cast<__half2*>(out + (size_t)rb * DOUT + col) = __floats2half2_rn(v2, v3);
        } else {
            float* out = (float*)outv;
            if (ra < N_NODES)
                *reinterpret_cast<float2*>(out + (size_t)ra * DOUT + col) = make_float2(v0, v1);
            if (rb < N_NODES)
                *reinterpret_cast<float2*>(out + (size_t)rb * DOUT + col) = make_float2(v2, v3);
        }
    }
}

// ---------------- launch ----------------
extern "C" void kernel_launch(void* const* d_in, const int* in_sizes, int n_in,
                              void* d_out, int out_size)
{
    const float* x        = (const float*)d_in[0];
    const int*   edge_src = (const int*)d_in[1];
    const int*   edge_dst = (const int*)d_in[2];

    const float* Wp[3]; const float* bp[3];
    const float* Ws[3]; const float* Wn[3]; const float* bb[3];
    for (int l = 0; l < 3; l++) {
        Wp[l] = (const float*)d_in[3 + 5 * l + 0];
        bp[l] = (const float*)d_in[3 + 5 * l + 1];
        Ws[l] = (const float*)d_in[3 + 5 * l + 2];
        Wn[l] = (const float*)d_in[3 + 5 * l + 3];
        bb[l] = (const float*)d_in[3 + 5 * l + 4];
    }

    float* out = (float*)d_out;

    __half* xd;  cudaGetSymbolAddress((void**)&xd, g_x);
    __half* h0d; cudaGetSymbolAddress((void**)&h0d, g_h0);
    __half* h1d; cudaGetSymbolAddress((void**)&h1d, g_h1);
    __half* xpd; cudaGetSymbolAddress((void**)&xpd, g_xp);
    __half* pld; cudaGetSymbolAddress((void**)&pld, g_pooled);
    __half* hsd; cudaGetSymbolAddress((void**)&hsd, g_hs);
    __half* wd;  cudaGetSymbolAddress((void**)&wd, g_w);
    int* curd;   cudaGetSymbolAddress((void**)&curd, g_cursor);

    const int TPB = 256;
    const int G1_X = (N_NODES + 127) / 128;   // 391
    const int G2_X = (N_NODES + 63) / 64;     // 782
    const int POOL_BLOCKS = (N_NODES * 32 + TPB - 1) / TPB;

    // dynamic smem sizes (bytes)
    const int SMEM1      = (128 * AST1 + 128 * BST64) * 2;           // 53248
    const int SMEM2_128  = (64 * AST1 + 128 * BST128) * 2;           // 52224
    const int SMEM2_64   = (64 * AST1 + 128 * BST64) * 2;            // 35840

    // one-time infra (stream/events are not device memory; results unaffected)
    static cudaStream_t s2 = nullptr;
    static cudaEvent_t eRoot, eCSR, ePrep, eH1, eJ1, eH2, eJ2, eH3;
    if (!s2) {
        cudaStreamCreateWithFlags(&s2, cudaStreamNonBlocking);
        cudaEventCreateWithFlags(&eRoot, cudaEventDisableTiming);
        cudaEventCreateWithFlags(&eCSR,  cudaEventDisableTiming);
        cudaEventCreateWithFlags(&ePrep, cudaEventDisableTiming);
        cudaEventCreateWithFlags(&eH1,   cudaEventDisableTiming);
        cudaEventCreateWithFlags(&eJ1,   cudaEventDisableTiming);
        cudaEventCreateWithFlags(&eH2,   cudaEventDisableTiming);
        cudaEventCreateWithFlags(&eJ2,   cudaEventDisableTiming);
        cudaEventCreateWithFlags(&eH3,   cudaEventDisableTiming);
        cudaFuncSetAttribute((const void*)fused1_kernel<128>,
                             cudaFuncAttributeMaxDynamicSharedMemorySize, SMEM1);
        cudaFuncSetAttribute((const void*)fused1_kernel<64>,
                             cudaFuncAttributeMaxDynamicSharedMemorySize, SMEM1);
        cudaFuncSetAttribute((const void*)fused2_kernel<128, true>,
                             cudaFuncAttributeMaxDynamicSharedMemorySize, SMEM2_128);
        cudaFuncSetAttribute((const void*)fused2_kernel<64, false>,
                             cudaFuncAttributeMaxDynamicSharedMemorySize, SMEM2_64);
    }

    WConv wc;
    wc.src[0] = Wp[0]; wc.off[0] = OFF_WP0; wc.n[0] = 16384;
    wc.src[1] = Wp[1]; wc.off[1] = OFF_WP1; wc.n[1] = 16384;
    wc.src[2] = Wp[2]; wc.off[2] = OFF_WP2; wc.n[2] = 16384;
    wc.src[3] = Ws[0]; wc.off[3] = OFF_WS0; wc.n[3] = 16384;
    wc.src[4] = Ws[1]; wc.off[4] = OFF_WS1; wc.n[4] = 16384;
    wc.src[5] = Ws[2]; wc.off[5] = OFF_WS2; wc.n[5] = 8192;
    wc.src[6] = Wn[0]; wc.off[6] = OFF_WN0; wc.n[6] = 16384;
    wc.src[7] = Wn[1]; wc.off[7] = OFF_WN1; wc.n[7] = 16384;
    wc.src[8] = Wn[2]; wc.off[8] = OFF_WN2; wc.n[8] = 8192;

    // ---- fork: CSR chain on s2, converts + layer-1 xp GEMM on legacy ----
    cudaMemsetAsync(curd, 0, N_NODES * sizeof(int));
    cudaEventRecord(eRoot, 0);
    cudaStreamWaitEvent(s2, eRoot, 0);
    count_deg_kernel<<<EDGE4_BLOCKS, TPB, 0, s2>>>((const int4*)edge_dst);
    scan_blocks_kernel<<<SCAN_BLOCKS, 256, 0, s2>>>();
    add_offsets_kernel<<<SCAN_BLOCKS, 256, 0, s2>>>();
    scatter_kernel<<<EDGE4_BLOCKS, TPB, 0, s2>>>((const int4*)edge_src, (const int4*)edge_dst);
    cudaEventRecord(eCSR, s2);

    prep_kernel<<<CVT_BLOCKS + WCVT_BLOCKS, TPB>>>((const float4*)x, wc);
    cudaEventRecord(ePrep, 0);

    // ---- layer 1: xp chunks on legacy; hs chunks on s2 after CSR+prep ----
    cudaStreamWaitEvent(s2, ePrep, 0);
    fused1_kernel<128><<<dim3(G1_X, 2), TPB, SMEM1, s2>>>(xd, wd + OFF_WP0, bp[0], wd + OFF_WS0, xpd, hsd, 2);
    cudaEventRecord(eH1, s2);

    fused1_kernel<128><<<dim3(G1_X, 2), TPB, SMEM1>>>(xd, wd + OFF_WP0, bp[0], wd + OFF_WS0, xpd, hsd, 0);
    cudaStreamWaitEvent(0, eCSR, 0);
    pool_kernel<<<POOL_BLOCKS, TPB>>>();
    cudaStreamWaitEvent(0, eH1, 0);
    fused2_kernel<128, true><<<G2_X, TPB, SMEM2_128>>>(pld, wd + OFF_WN0, bb[0], hsd, h0d);
    cudaEventRecord(eJ1, 0);

    // ---- layer 2: hs GEMM on s2 overlaps (xp GEMM -> pool) on legacy ----
    cudaStreamWaitEvent(s2, eJ1, 0);
    fused1_kernel<128><<<dim3(G1_X, 2), TPB, SMEM1, s2>>>(h0d, wd + OFF_WP1, bp[1], wd + OFF_WS1, xpd, hsd, 2);
    cudaEventRecord(eH2, s2);
    fused1_kernel<128><<<dim3(G1_X, 2), TPB, SMEM1>>>(h0d, wd + OFF_WP1, bp[1], wd + OFF_WS1, xpd, hsd, 0);
    pool_kernel<<<POOL_BLOCKS, TPB>>>();
    cudaStreamWaitEvent(0, eH2, 0);
    fused2_kernel<128, true><<<G2_X, TPB, SMEM2_128>>>(pld, wd + OFF_WN1, bb[1], hsd, h1d);
    cudaEventRecord(eJ2, 0);

    // ---- layer 3: same overlap; out fp32 ----
    cudaStreamWaitEvent(s2, eJ2, 0);
    fused1_kernel<64><<<dim3(G1_X, 1), TPB, SMEM1, s2>>>(h1d, wd + OFF_WP2, bp[2], wd + OFF_WS2, xpd, hsd, 2);
    cudaEventRecord(eH3, s2);
    fused1_kernel<64><<<dim3(G1_X, 2), TPB, SMEM1>>>(h1d, wd + OFF_WP2, bp[2], wd + OFF_WS2, xpd, hsd, 0);
    pool_kernel<<<POOL_BLOCKS, TPB>>>();
    cudaStreamWaitEvent(0, eH3, 0);
    fused2_kernel<64, false><<<G2_X, TPB, SMEM2_64>>>(pld, wd + OFF_WN2, bb[2], hsd, out);
}